// round 4
// baseline (speedup 1.0000x reference)
#include <cuda_runtime.h>
#include <cstdint>

// ---------------- problem constants ----------------
#define NB_ROWS   16384
#define N_IN      256
#define N_OUT     256
#define N_BASES   31
#define N_J       33          // 32 buckets + the all-zero bucket (xn == 1.0)
#define TB        112         // rows per block
#define RPG       28          // rows per row-group (4 groups of 64 o-threads)
#define NBLK      147         // ceil(16384/112)
#define BPAD      16576       // padded row count for RXJ (multiple of 32, >= 147*112)

// ---------------- device scratch (no allocation allowed) ----------------
__device__ float        g_W2[N_IN * N_J * N_OUT];     // [i][j][o]  8.65 MB
__device__ float        g_BWT[N_IN * N_OUT];          // [i][o]     256 KB
__device__ unsigned int g_RXJ[N_IN * BPAD];           // [i][row]: relu(x) fp32 with j in low 6 mantissa bits
__device__ unsigned int g_minU[N_IN];
__device__ unsigned int g_maxU[N_IN];
__device__ float        g_minv[N_IN];
__device__ float        g_rcp[N_IN];                  // RN(1 / (max-min+1e-8)) per column

// ---------------- helpers ----------------
__device__ __forceinline__ unsigned int enc_f(float f) {
    unsigned int u = __float_as_uint(f);
    return (u & 0x80000000u) ? ~u : (u | 0x80000000u);
}
__device__ __forceinline__ float dec_f(unsigned int e) {
    unsigned int u = (e & 0x80000000u) ? (e ^ 0x80000000u) : ~e;
    return __uint_as_float(u);
}

__device__ __forceinline__ unsigned long long pk2(float a, float b) {
    unsigned long long r;
    asm("mov.b64 %0, {%1, %2};" : "=l"(r) : "f"(a), "f"(b));
    return r;
}
__device__ __forceinline__ void fma2(unsigned long long& d, unsigned long long a, unsigned long long b) {
    asm("fma.rn.f32x2 %0, %1, %2, %0;" : "+l"(d) : "l"(a), "l"(b));
}
__device__ __forceinline__ void add2(unsigned long long& d, unsigned long long a) {
    asm("add.rn.f32x2 %0, %1, %0;" : "+l"(d) : "l"(a));
}
__device__ __forceinline__ float lo32(unsigned long long v) {
    return __uint_as_float((unsigned int)(v & 0xFFFFFFFFull));
}
__device__ __forceinline__ float hi32(unsigned long long v) {
    return __uint_as_float((unsigned int)(v >> 32));
}

// ---------------- K0: init min/max atomics ----------------
__global__ void k_init() {
    int t = threadIdx.x;
    g_minU[t] = 0xFFFFFFFFu;
    g_maxU[t] = 0x00000000u;
}

// ---------------- K1: per-column min/max (128 blocks x 128 rows) ----------------
__global__ void k_minmax(const float* __restrict__ x) {
    int c  = threadIdx.x;
    int r0 = blockIdx.x * 128;
    float mn = __int_as_float(0x7f800000);   // +inf
    float mx = __int_as_float(0xff800000);   // -inf
    for (int r = r0; r < r0 + 128; r++) {
        float v = x[r * N_IN + c];
        mn = fminf(mn, v);
        mx = fmaxf(mx, v);
    }
    atomicMin(&g_minU[c], enc_f(mn));
    atomicMax(&g_maxU[c], enc_f(mx));
}

// ---------------- K2: per-column reciprocal of denominator ----------------
// XLA's algebraic simplifier rewrites  div(A, broadcast(B))  into
// mul(A, broadcast(div(1, B))) , hoisting one correctly-rounded divide per
// column. Replicate that exactly: rcp = RN(1/d), then per-element mul.rn.
__global__ void k_denom() {
    int i = threadIdx.x;
    float mn = dec_f(g_minU[i]);
    float mx = dec_f(g_maxU[i]);
    float d  = __fadd_rn(__fsub_rn(mx, mn), 1e-8f);   // same op sequence as reference
    g_minv[i] = mn;
    g_rcp[i]  = __frcp_rn(d);                          // == div.rn.f32(1.0, d)
}

// ---------------- K3: bucketize + transpose -> RXJ[i][row] ----------------
__global__ void k_rxj(const float* __restrict__ x) {
    __shared__ unsigned int s[32][33];
    int tx = threadIdx.x, ty = threadIdx.y;
    int c0 = blockIdx.x * 32;
    int r0 = blockIdx.y * 32;
    int c  = c0 + tx;
    float mn = g_minv[c];
    float rc = g_rcp[c];
#pragma unroll
    for (int k = 0; k < 4; k++) {
        int r = r0 + ty + 8 * k;
        unsigned int w = 0u;
        if (r < NB_ROWS) {
            float v  = x[r * N_IN + c];
            // separate sub.rn then mul.rn — intrinsics forbid FMA contraction,
            // matching XLA's non-contracting elementwise codegen
            float xn = __fmul_rn(__fsub_rn(v, mn), rc);
            int j = (int)(xn * 32.0f);            // *32 exact; trunc == floor (xn >= 0)
            j = min(max(j, 0), 32);
            float rx = fmaxf(v, 0.0f);
            w = (__float_as_uint(rx) & 0xFFFFFFC0u) | (unsigned int)j;
        }
        s[ty + 8 * k][tx] = w;
    }
    __syncthreads();
#pragma unroll
    for (int k = 0; k < 4; k++) {
        int c2 = c0 + ty + 8 * k;
        int r2 = r0 + tx;
        g_RXJ[c2 * BPAD + r2] = s[tx][ty + 8 * k];
    }
}

// ---------------- K4: transpose base_weight [O][I] -> BWT [I][O] ----------------
__global__ void k_tbw(const float* __restrict__ bw) {
    __shared__ float s[32][33];
    int tx = threadIdx.x, ty = threadIdx.y;
    int a0 = blockIdx.y * 32;   // o dimension
    int b0 = blockIdx.x * 32;   // i dimension
#pragma unroll
    for (int k = 0; k < 4; k++)
        s[ty + 8 * k][tx] = bw[(a0 + ty + 8 * k) * N_IN + b0 + tx];
    __syncthreads();
#pragma unroll
    for (int k = 0; k < 4; k++)
        g_BWT[(b0 + ty + 8 * k) * N_OUT + a0 + tx] = s[tx][ty + 8 * k];
}

// ---------------- K5: build W2[i][j][o] ----------------
__global__ void k_w2(const float* __restrict__ sw, const float* __restrict__ sc) {
    int i = blockIdx.x;
    int o = threadIdx.x;
    float s = sc[o * N_IN + i];
    float w[N_BASES];
#pragma unroll
    for (int k = 0; k < N_BASES; k++)
        w[k] = sw[o * (N_IN * N_BASES) + i * N_BASES + k] * s;
    float* dst = g_W2 + (i * N_J) * N_OUT + o;
#pragma unroll
    for (int j = 0; j < 32; j++) {
        float a = 0.0f;
#pragma unroll
        for (int l = 0; l < 5; l++) {
            int shift = j >> (5 - l);
            int half  = (j >> (4 - l)) & 1;
            int k     = (1 << l) - 1 + shift;
            a += half ? -w[k] : w[k];
        }
        dst[j * N_OUT] = a;
    }
    dst[32 * N_OUT] = 0.0f;   // all-zero bucket (xn == 1.0)
}

// ---------------- K6: main fused kernel ----------------
// 147 blocks x 256 threads. Thread = (o4 = tid&63 -> 4 outputs, g = tid>>6 -> row group of 28 rows).
// Per i: one coalesced bw float4, one broadcast uint4 per 4 rows, one L1-resident LDG.128 gather per row.
__global__ __launch_bounds__(256, 1) void k_main(float* __restrict__ out) {
    int tid   = threadIdx.x;
    int o4    = tid & 63;
    int g     = tid >> 6;
    int rbase = blockIdx.x * TB + g * RPG;

    unsigned long long acc[RPG][2];
#pragma unroll
    for (int r = 0; r < RPG; r++) { acc[r][0] = 0ull; acc[r][1] = 0ull; }

    const ulonglong2* __restrict__ W2v = reinterpret_cast<const ulonglong2*>(g_W2);
    const float4*     __restrict__ BWv = reinterpret_cast<const float4*>(g_BWT);
    const uint4*      __restrict__ RXv = reinterpret_cast<const uint4*>(g_RXJ);

    for (int i = 0; i < N_IN; i++) {
        float4 bw = BWv[i * (N_OUT / 4) + o4];
        unsigned long long bwp0 = pk2(bw.x, bw.y);
        unsigned long long bwp1 = pk2(bw.z, bw.w);
        const ulonglong2* slice = W2v + (size_t)i * (N_J * (N_OUT / 4)) + o4;
        const uint4*      rxr   = RXv + i * (BPAD / 4) + (rbase >> 2);
#pragma unroll
        for (int c = 0; c < RPG / 4; c++) {
            uint4 q = rxr[c];                       // broadcast: rows rbase+4c .. +3
            unsigned int ws[4] = { q.x, q.y, q.z, q.w };
#pragma unroll
            for (int u = 0; u < 4; u++) {
                unsigned int w = ws[u];
                ulonglong2 gv = slice[(w & 63u) * (N_OUT / 4)];        // gather, L1 hit
                unsigned long long rxx = pk2(__uint_as_float(w), __uint_as_float(w));
                fma2(acc[4 * c + u][0], bwp0, rxx);
                add2(acc[4 * c + u][0], gv.x);
                fma2(acc[4 * c + u][1], bwp1, rxx);
                add2(acc[4 * c + u][1], gv.y);
            }
        }
        if ((i & 7) == 7) __syncthreads();          // keep warps on the same L1 slice
    }

#pragma unroll
    for (int r = 0; r < RPG; r++) {
        int row = rbase + r;
        if (row < NB_ROWS) {
            float4 o;
            o.x = lo32(acc[r][0]); o.y = hi32(acc[r][0]);
            o.z = lo32(acc[r][1]); o.w = hi32(acc[r][1]);
            reinterpret_cast<float4*>(out)[row * (N_OUT / 4) + o4] = o;
        }
    }
}

// ---------------- launch ----------------
extern "C" void kernel_launch(void* const* d_in, const int* in_sizes, int n_in,
                              void* d_out, int out_size) {
    const float* x  = (const float*)d_in[0];   // [16384, 256]
    const float* bw = (const float*)d_in[1];   // [256, 256]
    const float* sw = (const float*)d_in[2];   // [256, 256, 31]
    const float* sc = (const float*)d_in[3];   // [256, 256]
    float* out = (float*)d_out;

    k_init  <<<1, 256>>>();
    k_minmax<<<128, 256>>>(x);
    k_denom <<<1, 256>>>();
    k_rxj   <<<dim3(8, BPAD / 32), dim3(32, 8)>>>(x);
    k_tbw   <<<dim3(8, 8), dim3(32, 8)>>>(bw);
    k_w2    <<<256, 256>>>(sw, sc);
    k_main  <<<NBLK, 256>>>(out);
}